// round 14
// baseline (speedup 1.0000x reference)
#include <cuda_runtime.h>
#include <cuda_bf16.h>
#include <cstdint>
#include <cstddef>

#define B_   512
#define T_   2048
#define NP   800          // C*M pairs
#define TPB  256
#define NBLK 256          // B_/2, 2 batches per block, 2 CTAs per SM

#define L2E     1.4426950408889634f
#define TWO_L2E 2.8853900817779268f

// ---- shared layout (float offsets), 27612 floats = 107.9 KB per CTA ----
#define OFF_SQ   0        // Sq[4 quad][800][4] : S quads transposed, *2*log2e (12800 f)
#define OFF_AT   12800    // float at[16][804]  : A transposed, padded         (12864 f)
#define OFF_W    25664    // float w[2][808]    : stride 808                   ( 1616 f)
#define OFF_RED  27280    // float red[2][8][16]                               (  256 f)
#define OFF_ST   27536    // float st[2][20]                                   (   40 f)
#define OFF_GATE 27576    // float gate[2][2][8]                               (   32 f)
#define OFF_XB   27608    // float xb[2][2]                                    (    4 f)
#define SMEM_FLOATS 27612
#define SMEM_BYTES  (SMEM_FLOATS * 4)

typedef unsigned long long u64;

__device__ float g_gate[(size_t)B_ * T_ * 8];

__device__ __forceinline__ float ex2f(float a)
{
    float r;
    asm("ex2.approx.ftz.f32 %0, %1;" : "=f"(r) : "f"(a));
    return r;
}
__device__ __forceinline__ u64 fma2(u64 b, u64 c, u64 a)   // b*c + a
{
    u64 d;
    asm("fma.rn.f32x2 %0, %1, %2, %3;" : "=l"(d) : "l"(b), "l"(c), "l"(a));
    return d;
}
__device__ __forceinline__ u64 mul2(u64 a, u64 b)
{
    u64 d;
    asm("mul.rn.f32x2 %0, %1, %2;" : "=l"(d) : "l"(a), "l"(b));
    return d;
}
__device__ __forceinline__ float2 upk(u64 a)
{
    float2 f;
    asm("mov.b64 {%0, %1}, %2;" : "=f"(f.x), "=f"(f.y) : "l"(a));
    return f;
}
__device__ __forceinline__ u64 pk2(float lo, float hi)
{
    u64 d;
    asm("mov.b64 %0, {%1, %2};" : "=l"(d) : "f"(lo), "f"(hi));
    return d;
}

// ---------------------------------------------------------------------------
// Kernel 1: gate[b,t,:] = softmax(relu(x*W1+b1) @ W2 + b2). One thread per (b,t).
// ---------------------------------------------------------------------------
__global__ void gate_kernel(const float* __restrict__ x,
                            const float* __restrict__ W1,
                            const float* __restrict__ b1,
                            const float* __restrict__ W2,
                            const float* __restrict__ b2)
{
    int idx = blockIdx.x * blockDim.x + threadIdx.x;
    if (idx >= B_ * T_) return;
    float xv = x[idx];

    float lg[8];
#pragma unroll
    for (int c = 0; c < 8; c++) lg[c] = __ldg(&b2[c]);
#pragma unroll
    for (int jj = 0; jj < 16; jj++) {
        float h = fmaxf(fmaf(xv, __ldg(&W1[jj]), __ldg(&b1[jj])), 0.0f);
#pragma unroll
        for (int c = 0; c < 8; c++)
            lg[c] = fmaf(h, __ldg(&W2[jj * 8 + c]), lg[c]);
    }
    float m = lg[0];
#pragma unroll
    for (int c = 1; c < 8; c++) m = fmaxf(m, lg[c]);
    float e[8], ssum = 0.0f;
#pragma unroll
    for (int c = 0; c < 8; c++) { e[c] = __expf(lg[c] - m); ssum += e[c]; }
    float inv = 1.0f / ssum;
#pragma unroll
    for (int c = 0; c < 8; c++) g_gate[(size_t)idx * 8 + c] = e[c] * inv;
}

// ---------------------------------------------------------------------------
// Kernel 2: recurrent scan. 256 blocks x 256 threads, 2 batches per block,
// 2 CTAs per SM. Barriers sync only 256 threads; the co-resident CTA keeps
// issuing through them (cross-CTA latency hiding with full registers).
// uk lives in per-thread registers (pairs are static across t).
// ---------------------------------------------------------------------------
__global__ void __launch_bounds__(TPB, 2)
scan_kernel(const float* __restrict__ x,
            const float* __restrict__ S,
            const float* __restrict__ U,
            const float* __restrict__ A,
            float* __restrict__ out)
{
    extern __shared__ float sm[];
    const int tid = threadIdx.x;
    const int b0  = blockIdx.x * 2;

    // ---------------- stage S', A^T ----------------
    for (int idx = tid; idx < NP * 16; idx += TPB) {
        int p = idx >> 4, k = idx & 15;
        sm[OFF_SQ + (k >> 2) * 3200 + (p << 2) + (k & 3)] = TWO_L2E * S[idx];
        sm[OFF_AT + k * 804 + p] = A[idx];
    }
    if (tid < 16) {
        sm[OFF_GATE + tid] = g_gate[((size_t)(b0 + (tid >> 3)) * T_) * 8 + (tid & 7)];
        if (tid < 2) sm[OFF_XB + tid] = x[(size_t)(b0 + tid) * T_];
    }

    const int b    = tid & 1;    // phase A batch
    const int pp   = tid >> 1;   // phase A dpair lane (0..127)
    const int nn   = tid & 15;   // phase B output dim
    const int jj   = tid >> 4;   // phase B chunk lane (0..15)
    const int lane = tid & 31;
    const int wrp  = tid >> 5;   // 0..7

    // -------- uk register cache: this thread's 4 dpairs (8 pairs), static ----
    // dpairs: pp, pp+128, pp+256, 272+pp (4th valid only when pp>=112;
    // computed unconditionally — reads stay in-bounds and value is unused).
    u64 uka[4], ukb[4];
    {
        int mydp[4] = { pp, pp + 128, pp + 256, 272 + pp };
#pragma unroll
        for (int i = 0; i < 4; i++) {
#pragma unroll
            for (int h = 0; h < 2; h++) {
                int p = 2 * mydp[i] + h;
                float acc = 0.0f;
#pragma unroll
                for (int k = 0; k < 16; k++) {
                    float v = __ldg(&S[p * 16 + k]);
                    acc = fmaf(v, v, acc);
                }
                float uv = __ldg(&U[p]);
                u64 r = pk2(TWO_L2E * uv, L2E * fmaf(uv, uv, acc));
                if (h == 0) uka[i] = r; else ukb[i] = r;
            }
        }
    }
    __syncthreads();

    const ulonglong2* Sq2 = (const ulonglong2*)(sm + OFF_SQ);
    const ulonglong2* At2 = (const ulonglong2*)(sm + OFF_AT + nn * 804);
    const ulonglong2* Wb2 = (const ulonglong2*)(sm + OFF_W);

    // packed state (8 x f32x2); xv = raw x_t
    u64 s0 = 0, s1 = 0, s2 = 0, s3 = 0, s4 = 0, s5 = 0, s6 = 0, s7 = 0;
    float xv = sm[OFF_XB + b];
    u64 hs = pk2(-L2E * xv * xv, 0.0f);
    u64 xp = pk2(xv, -1.0f);

    for (int t = 0; t < T_; t++) {
        const int par = t & 1;

        // next-step gate/x loads (committed after bar1, consumed at step end)
        float gpre = 0.f, xpre = 0.f;
        const bool pf = (tid < 16) && (t + 1 < T_);
        if (pf) {
            gpre = g_gate[((size_t)(b0 + (tid >> 3)) * T_ + (t + 1)) * 8 + (tid & 7)];
            if (tid < 2) xpre = x[(size_t)(b0 + tid) * T_ + (t + 1)];
        }

        // ---------------- phase A: pairs (2dp, 2dp+1) ----------------
        {
            const float* gsh = sm + OFF_GATE + par * 16 + b * 8;

            auto dpair = [&](int dp, int ci, u64 ua, u64 ub) {
                const int p0 = 2 * dp;
                ulonglong2 q0a = Sq2[p0],        q0b = Sq2[p0 + 1];
                ulonglong2 q1a = Sq2[800 + p0],  q1b = Sq2[801 + p0];
                ulonglong2 q2a = Sq2[1600 + p0], q2b = Sq2[1601 + p0];
                ulonglong2 q3a = Sq2[2400 + p0], q3b = Sq2[2401 + p0];
                float g = gsh[ci];

                u64 da = fma2(ua, xp, hs);        // (u2*xv - h', -k')
                da = fma2(q0a.x, s0, da);
                da = fma2(q0a.y, s1, da);
                da = fma2(q1a.x, s2, da);
                da = fma2(q1a.y, s3, da);
                da = fma2(q2a.x, s4, da);
                da = fma2(q2a.y, s5, da);
                da = fma2(q3a.x, s6, da);
                da = fma2(q3a.y, s7, da);
                float2 fa = upk(da);
                float e0 = fa.x + fa.y;

                u64 db = fma2(ub, xp, hs);
                db = fma2(q0b.x, s0, db);
                db = fma2(q0b.y, s1, db);
                db = fma2(q1b.x, s2, db);
                db = fma2(q1b.y, s3, db);
                db = fma2(q2b.x, s4, db);
                db = fma2(q2b.y, s5, db);
                db = fma2(q3b.x, s6, db);
                db = fma2(q3b.y, s7, db);
                float2 fb = upk(db);
                float e1 = fb.x + fb.y;

                *(float2*)(sm + OFF_W + b * 808 + p0) =
                    make_float2(g * ex2f(e0), g * ex2f(e1));
            };
#pragma unroll
            for (int i = 0; i < 3; i++) {
                int dp = pp + 128 * i;
                dpair(dp, (unsigned)dp / 50u, uka[i], ukb[i]);
            }
            if (pp >= 112) dpair(272 + pp, 7, uka[3], ukb[3]);
        }
        __syncthreads();                             // bar 1

        // commit prefetched gate/x for t+1
        if (pf) {
            sm[OFF_GATE + (par ^ 1) * 16 + tid] = gpre;
            if (tid < 2) sm[OFF_XB + (par ^ 1) * 2 + tid] = xpre;
        }

        // ---------------- phase B: s_new[b][n] = sum_p w[b][p]*A[p][n] -------
        u64 c0 = 0, c1 = 0;
        auto chunkB = [&](int p4) {
            ulonglong2 av = At2[p4];
            ulonglong2 w0 = Wb2[p4];
            ulonglong2 w1 = Wb2[202 + p4];
            c0 = fma2(av.x, w0.x, c0); c0 = fma2(av.y, w0.y, c0);
            c1 = fma2(av.x, w1.x, c1); c1 = fma2(av.y, w1.y, c1);
        };
#pragma unroll
        for (int i = 0; i < 12; i++) chunkB(jj + 16 * i);        // chunks 0..191
        if (jj < 8) chunkB(192 + jj);                            // tail 192..199

        float2 f0 = upk(c0), f1 = upk(c1);
        float a0 = f0.x + f0.y, a1 = f1.x + f1.y;
        a0 += __shfl_xor_sync(0xffffffffu, a0, 16);
        a1 += __shfl_xor_sync(0xffffffffu, a1, 16);
        if (lane < 16) {
            sm[OFF_RED +       wrp * 16 + lane] = a0;
            sm[OFF_RED + 128 + wrp * 16 + lane] = a1;
        }
        __syncthreads();                             // bar 2

        // ---------------- final reduce + output (all 256 threads) ------------
        {
            const int bb = tid >> 7, n2 = (tid >> 3) & 15, g = tid & 7;
            float v = sm[OFF_RED + bb * 128 + g * 16 + n2];
            v += __shfl_xor_sync(0xffffffffu, v, 1);
            v += __shfl_xor_sync(0xffffffffu, v, 2);
            v += __shfl_xor_sync(0xffffffffu, v, 4);
            if (g == 0) {
                sm[OFF_ST + bb * 20 + n2] = v;
                if (n2 == 15) out[(size_t)(b0 + bb) * T_ + t] = v;
            }
        }
        __syncthreads();                             // bar 3

        // reload packed state; recompute h', xp locally
        {
            const ulonglong2* st2 = (const ulonglong2*)(sm + OFF_ST + b * 20);
            ulonglong2 u0 = st2[0], u1 = st2[1], u2 = st2[2], u3 = st2[3];
            s0 = u0.x; s1 = u0.y; s2 = u1.x; s3 = u1.y;
            s4 = u2.x; s5 = u2.y; s6 = u3.x; s7 = u3.y;
            xv = sm[OFF_XB + (par ^ 1) * 2 + b];
            u64 acc = mul2(s0, s0);
            acc = fma2(s1, s1, acc);
            acc = fma2(s2, s2, acc);
            acc = fma2(s3, s3, acc);
            acc = fma2(s4, s4, acc);
            acc = fma2(s5, s5, acc);
            acc = fma2(s6, s6, acc);
            acc = fma2(s7, s7, acc);
            float2 fs = upk(acc);
            float hv = fmaf(xv, xv, fs.x + fs.y);
            hs = pk2(-L2E * hv, 0.0f);
            xp = pk2(xv, -1.0f);
        }
    }
}

// ---------------------------------------------------------------------------
extern "C" void kernel_launch(void* const* d_in, const int* in_sizes, int n_in,
                              void* d_out, int out_size)
{
    const float* x  = (const float*)d_in[0];
    const float* S  = (const float*)d_in[1];
    const float* U  = (const float*)d_in[2];
    const float* A  = (const float*)d_in[3];
    const float* W1 = (const float*)d_in[4];
    const float* b1 = (const float*)d_in[5];
    const float* W2 = (const float*)d_in[6];
    const float* b2 = (const float*)d_in[7];
    float* out = (float*)d_out;

    cudaFuncSetAttribute(scan_kernel,
                         cudaFuncAttributeMaxDynamicSharedMemorySize, SMEM_BYTES);

    gate_kernel<<<(B_ * T_ + 255) / 256, 256>>>(x, W1, b1, W2, b2);
    scan_kernel<<<NBLK, TPB, SMEM_BYTES>>>(x, S, U, A, out);
}

// round 15
// speedup vs baseline: 1.2793x; 1.2793x over previous
#include <cuda_runtime.h>
#include <cuda_bf16.h>
#include <cstdint>
#include <cstddef>

#define B_   512
#define T_   2048
#define NP   800          // C*M pairs
#define TPB  512
#define NBLK 128          // B_/4, 4 batches per block

#define L2E     1.4426950408889634f
#define TWO_L2E 2.8853900817779268f

// ---- shared layout (float offsets) ----
#define OFF_SQ   0        // Sq[4 quad][800][4] : S quads transposed, *2*log2e (12800 f)
#define OFF_AT   12800    // float at[16][804]  : A transposed, padded         (12864 f)
#define OFF_UK   25664    // float2 uk[800]     : (2*l2e*U, l2e*(|S|^2+U^2))   ( 1600 f)
#define OFF_W    27264    // float w[4][808]    : stride 808                   ( 3232 f)
#define OFF_RED  30496    // float red[2 grp][4 b][8 wg][16]                   ( 1024 f)
#define OFF_ST   31520    // float st_p[2 par][2 grp][4 b][20]                 (  320 f)
#define OFF_GATE 31840    // float gate[2 par][4 b][8]                         (   64 f)
#define OFF_XB   31904    // float xb[2 par][4]                                (    8 f)
#define SMEM_FLOATS 31912
#define SMEM_BYTES  (SMEM_FLOATS * 4)

typedef unsigned long long u64;

__device__ float g_gate[(size_t)B_ * T_ * 8];

__device__ __forceinline__ float ex2f(float a)
{
    float r;
    asm("ex2.approx.ftz.f32 %0, %1;" : "=f"(r) : "f"(a));
    return r;
}
__device__ __forceinline__ u64 fma2(u64 b, u64 c, u64 a)   // b*c + a
{
    u64 d;
    asm("fma.rn.f32x2 %0, %1, %2, %3;" : "=l"(d) : "l"(b), "l"(c), "l"(a));
    return d;
}
__device__ __forceinline__ u64 mul2(u64 a, u64 b)
{
    u64 d;
    asm("mul.rn.f32x2 %0, %1, %2;" : "=l"(d) : "l"(a), "l"(b));
    return d;
}
__device__ __forceinline__ u64 add2(u64 a, u64 b)
{
    u64 d;
    asm("add.rn.f32x2 %0, %1, %2;" : "=l"(d) : "l"(a), "l"(b));
    return d;
}
__device__ __forceinline__ float2 upk(u64 a)
{
    float2 f;
    asm("mov.b64 {%0, %1}, %2;" : "=f"(f.x), "=f"(f.y) : "l"(a));
    return f;
}
__device__ __forceinline__ u64 pk2(float lo, float hi)
{
    u64 d;
    asm("mov.b64 %0, {%1, %2};" : "=l"(d) : "f"(lo), "f"(hi));
    return d;
}
__device__ __forceinline__ void gbar(int id)
{
    asm volatile("bar.sync %0, 256;" :: "r"(id) : "memory");
}

// ---------------------------------------------------------------------------
// Kernel 1: gate[b,t,:] = softmax(relu(x*W1+b1) @ W2 + b2). One thread per (b,t).
// ---------------------------------------------------------------------------
__global__ void gate_kernel(const float* __restrict__ x,
                            const float* __restrict__ W1,
                            const float* __restrict__ b1,
                            const float* __restrict__ W2,
                            const float* __restrict__ b2)
{
    int idx = blockIdx.x * blockDim.x + threadIdx.x;
    if (idx >= B_ * T_) return;
    float xv = x[idx];

    float lg[8];
#pragma unroll
    for (int c = 0; c < 8; c++) lg[c] = __ldg(&b2[c]);
#pragma unroll
    for (int jj = 0; jj < 16; jj++) {
        float h = fmaxf(fmaf(xv, __ldg(&W1[jj]), __ldg(&b1[jj])), 0.0f);
#pragma unroll
        for (int c = 0; c < 8; c++)
            lg[c] = fmaf(h, __ldg(&W2[jj * 8 + c]), lg[c]);
    }
    float m = lg[0];
#pragma unroll
    for (int c = 1; c < 8; c++) m = fmaxf(m, lg[c]);
    float e[8], ssum = 0.0f;
#pragma unroll
    for (int c = 0; c < 8; c++) { e[c] = __expf(lg[c] - m); ssum += e[c]; }
    float inv = 1.0f / ssum;
#pragma unroll
    for (int c = 0; c < 8; c++) g_gate[(size_t)idx * 8 + c] = e[c] * inv;
}

// ---------------------------------------------------------------------------
// Kernel 2: recurrent scan. 128 blocks x 512 threads, 4 batches per block.
// Two 256-thread groups split along the PAIR axis (group g owns pairs
// [400g, 400g+400)). Group-local named barriers for W and red; ONE full
// __syncthreads per step at the partial-state exchange. st_p/gate/x are
// parity double-buffered so cross-group access is race-free.
// ---------------------------------------------------------------------------
__global__ void __launch_bounds__(TPB, 1)
scan_kernel(const float* __restrict__ x,
            const float* __restrict__ S,
            const float* __restrict__ U,
            const float* __restrict__ A,
            float* __restrict__ out)
{
    extern __shared__ float sm[];
    const int tid = threadIdx.x;
    const int b0  = blockIdx.x * 4;

    // ---------------- stage S', A^T, (u2, k') ----------------
    for (int idx = tid; idx < NP * 16; idx += TPB) {
        int p = idx >> 4, k = idx & 15;
        sm[OFF_SQ + (k >> 2) * 3200 + (p << 2) + (k & 3)] = TWO_L2E * S[idx];
        sm[OFF_AT + k * 804 + p] = A[idx];
    }
    for (int p = tid; p < NP; p += TPB) {
        float acc = 0.0f;
#pragma unroll
        for (int k = 0; k < 16; k++) { float v = S[p * 16 + k]; acc = fmaf(v, v, acc); }
        float uv = U[p];
        sm[OFF_UK + 2 * p]     = TWO_L2E * uv;
        sm[OFF_UK + 2 * p + 1] = L2E * fmaf(uv, uv, acc);
    }
    if (tid < 32) {
        sm[OFF_GATE + tid] = g_gate[((size_t)(b0 + (tid >> 3)) * T_) * 8 + (tid & 7)];
        if (tid < 4) sm[OFF_XB + tid] = x[(size_t)(b0 + tid) * T_];
    }
    __syncthreads();

    const int grp  = tid >> 8;        // 0 / 1 : pair-half group
    const int gtid = tid & 255;
    const int b    = gtid & 3;        // phase A batch
    const int pp2  = gtid >> 2;       // phase A dpair lane within group (0..63)
    const int nn   = gtid & 15;       // phase B output dim
    const int jjg  = gtid >> 4;       // phase B chunk lane within group (0..15)
    const int lane = tid & 31;
    const int wg   = (gtid >> 5);     // warp within group (0..7)
    const int barid = 1 + grp;

    const ulonglong2* Sq2 = (const ulonglong2*)(sm + OFF_SQ);
    const ulonglong2* At2 = (const ulonglong2*)(sm + OFF_AT + nn * 804);
    const ulonglong2* Wb2 = (const ulonglong2*)(sm + OFF_W);

    // -------- A register cache: 6 static chunks in this group's half --------
    ulonglong2 Ac[6];
#pragma unroll
    for (int i = 0; i < 6; i++) Ac[i] = At2[grp * 100 + jjg + 16 * i];

    // packed state (8 x f32x2); xv = raw x_t
    u64 s0 = 0, s1 = 0, s2 = 0, s3 = 0, s4 = 0, s5 = 0, s6 = 0, s7 = 0;
    float xv = sm[OFF_XB + b];
    u64 hs = pk2(-L2E * xv * xv, 0.0f);
    u64 xp = pk2(xv, -1.0f);

    for (int t = 0; t < T_; t++) {
        const int par = t & 1;

        // next-step gate/x loads (group-0 warp 0; committed before full bar)
        float gpre = 0.f, xpre = 0.f;
        const bool pf = (tid < 32) && (t + 1 < T_);
        if (pf) {
            gpre = g_gate[((size_t)(b0 + (tid >> 3)) * T_ + (t + 1)) * 8 + (tid & 7)];
            if (tid < 4) xpre = x[(size_t)(b0 + tid) * T_ + (t + 1)];
        }

        // ---------------- phase A: this group's dpairs ----------------
        {
            const float* gsh = sm + OFF_GATE + par * 32 + b * 8;

            auto dpair = [&](int dp) {
                const int ci = (unsigned)dp / 50u;
                const int p0 = 2 * dp;
                ulonglong2 q0a = Sq2[p0],        q0b = Sq2[p0 + 1];
                ulonglong2 q1a = Sq2[800 + p0],  q1b = Sq2[801 + p0];
                ulonglong2 q2a = Sq2[1600 + p0], q2b = Sq2[1601 + p0];
                ulonglong2 q3a = Sq2[2400 + p0], q3b = Sq2[2401 + p0];
                ulonglong2 ukp = *(const ulonglong2*)(sm + OFF_UK + 4 * dp);
                float g = gsh[ci];

                u64 da = fma2(ukp.x, xp, hs);     // (u2*xv - h', -k')
                da = fma2(q0a.x, s0, da);
                da = fma2(q0a.y, s1, da);
                da = fma2(q1a.x, s2, da);
                da = fma2(q1a.y, s3, da);
                da = fma2(q2a.x, s4, da);
                da = fma2(q2a.y, s5, da);
                da = fma2(q3a.x, s6, da);
                da = fma2(q3a.y, s7, da);
                float2 fa = upk(da);
                float e0 = fa.x + fa.y;

                u64 db = fma2(ukp.y, xp, hs);
                db = fma2(q0b.x, s0, db);
                db = fma2(q0b.y, s1, db);
                db = fma2(q1b.x, s2, db);
                db = fma2(q1b.y, s3, db);
                db = fma2(q2b.x, s4, db);
                db = fma2(q2b.y, s5, db);
                db = fma2(q3b.x, s6, db);
                db = fma2(q3b.y, s7, db);
                float2 fb = upk(db);
                float e1 = fb.x + fb.y;

                *(float2*)(sm + OFF_W + b * 808 + p0) =
                    make_float2(g * ex2f(e0), g * ex2f(e1));
            };
#pragma unroll
            for (int i = 0; i < 3; i++) dpair(grp * 200 + pp2 + 64 * i);
            if (pp2 >= 56) dpair(grp * 200 + 136 + pp2);   // local 192..199
        }
        gbar(barid);                                 // group bar 1: W half ready

        // commit prefetched gate/x for t+1 (before the full barrier)
        if (pf) {
            sm[OFF_GATE + (par ^ 1) * 32 + tid] = gpre;
            if (tid < 4) sm[OFF_XB + (par ^ 1) * 4 + tid] = xpre;
        }

        // ---------------- phase B: partial s_new over this group's pairs -----
        u64 c0 = 0, c1 = 0, c2 = 0, c3 = 0;
        auto chunkB = [&](int p4, ulonglong2 av) {
            ulonglong2 w0 = Wb2[p4];
            ulonglong2 w1 = Wb2[202 + p4];
            ulonglong2 w2 = Wb2[404 + p4];
            ulonglong2 w3 = Wb2[606 + p4];
            c0 = fma2(av.x, w0.x, c0); c0 = fma2(av.y, w0.y, c0);
            c1 = fma2(av.x, w1.x, c1); c1 = fma2(av.y, w1.y, c1);
            c2 = fma2(av.x, w2.x, c2); c2 = fma2(av.y, w2.y, c2);
            c3 = fma2(av.x, w3.x, c3); c3 = fma2(av.y, w3.y, c3);
        };
#pragma unroll
        for (int i = 0; i < 6; i++) chunkB(grp * 100 + jjg + 16 * i, Ac[i]);
        if (jjg < 4) {
            int p4 = grp * 100 + 96 + jjg;           // local 96..99
            chunkB(p4, At2[p4]);
        }

        float2 f0 = upk(c0), f1 = upk(c1), f2 = upk(c2), f3 = upk(c3);
        float a0 = f0.x + f0.y, a1 = f1.x + f1.y, a2 = f2.x + f2.y, a3 = f3.x + f3.y;
        a0 += __shfl_xor_sync(0xffffffffu, a0, 16);
        a1 += __shfl_xor_sync(0xffffffffu, a1, 16);
        a2 += __shfl_xor_sync(0xffffffffu, a2, 16);
        a3 += __shfl_xor_sync(0xffffffffu, a3, 16);
        if (lane < 16) {
            float* rg = sm + OFF_RED + grp * 512 + wg * 16 + lane;
            rg[0]   = a0;
            rg[128] = a1;
            rg[256] = a2;
            rg[384] = a3;
        }
        gbar(barid);                                 // group bar 2: red ready

        // ---------------- group-local final reduce -> partial state ----------
        {
            const int bb = gtid >> 6, n2 = (gtid >> 2) & 15, gg = gtid & 3;
            const float* r = sm + OFF_RED + grp * 512 + bb * 128 + n2;
            float v = r[gg * 32] + r[gg * 32 + 16];  // warps 2gg, 2gg+1
            v += __shfl_xor_sync(0xffffffffu, v, 1);
            v += __shfl_xor_sync(0xffffffffu, v, 2);
            if (gg == 0)
                sm[OFF_ST + par * 160 + grp * 80 + bb * 20 + n2] = v;
        }
        __syncthreads();                             // FULL bar: exchange partials

        // ---------------- combine partials, output, state reload -------------
        {
            const float* base = sm + OFF_ST + par * 160;
            if (tid < 4)
                out[(size_t)(b0 + tid) * T_ + t] = base[tid * 20 + 15]
                                                 + base[80 + tid * 20 + 15];
            const ulonglong2* pa = (const ulonglong2*)(base + b * 20);
            const ulonglong2* pb = (const ulonglong2*)(base + 80 + b * 20);
            ulonglong2 a0v = pa[0], a1v = pa[1], a2v = pa[2], a3v = pa[3];
            ulonglong2 b0v = pb[0], b1v = pb[1], b2v = pb[2], b3v = pb[3];
            s0 = add2(a0v.x, b0v.x); s1 = add2(a0v.y, b0v.y);
            s2 = add2(a1v.x, b1v.x); s3 = add2(a1v.y, b1v.y);
            s4 = add2(a2v.x, b2v.x); s5 = add2(a2v.y, b2v.y);
            s6 = add2(a3v.x, b3v.x); s7 = add2(a3v.y, b3v.y);
            xv = sm[OFF_XB + (par ^ 1) * 4 + b];
            u64 acc = mul2(s0, s0);
            acc = fma2(s1, s1, acc);
            acc = fma2(s2, s2, acc);
            acc = fma2(s3, s3, acc);
            acc = fma2(s4, s4, acc);
            acc = fma2(s5, s5, acc);
            acc = fma2(s6, s6, acc);
            acc = fma2(s7, s7, acc);
            float2 fs = upk(acc);
            float hv = fmaf(xv, xv, fs.x + fs.y);
            hs = pk2(-L2E * hv, 0.0f);
            xp = pk2(xv, -1.0f);
        }
    }
}

// ---------------------------------------------------------------------------
extern "C" void kernel_launch(void* const* d_in, const int* in_sizes, int n_in,
                              void* d_out, int out_size)
{
    const float* x  = (const float*)d_in[0];
    const float* S  = (const float*)d_in[1];
    const float* U  = (const float*)d_in[2];
    const float* A  = (const float*)d_in[3];
    const float* W1 = (const float*)d_in[4];
    const float* b1 = (const float*)d_in[5];
    const float* W2 = (const float*)d_in[6];
    const float* b2 = (const float*)d_in[7];
    float* out = (float*)d_out;

    cudaFuncSetAttribute(scan_kernel,
                         cudaFuncAttributeMaxDynamicSharedMemorySize, SMEM_BYTES);

    gate_kernel<<<(B_ * T_ + 255) / 256, 256>>>(x, W1, b1, W2, b2);
    scan_kernel<<<NBLK, TPB, SMEM_BYTES>>>(x, S, U, A, out);
}

// round 16
// speedup vs baseline: 1.4201x; 1.1100x over previous
#include <cuda_runtime.h>
#include <cuda_bf16.h>
#include <cstdint>
#include <cstddef>

#define B_   512
#define T_   2048
#define NP   800          // C*M pairs
#define TPB  512
#define NBLK 128          // B_/4, 4 batches per block

#define L2E     1.4426950408889634f
#define TWO_L2E 2.8853900817779268f

// ---- shared layout (float offsets) ----
#define OFF_SQ   0        // Sq[4 quad][800][4] : S quads transposed, *2*log2e (12800 f)
#define OFF_AT   12800    // float at[16][804]  : A transposed, padded         (12864 f)
#define OFF_UK   25664    // float2 uk[800]     : (2*l2e*U, l2e*(|S|^2+U^2))   ( 1600 f)
#define OFF_W    27264    // float w[4][808]    : stride 808                   ( 3232 f)
#define OFF_RED  30496    // float red[4][16][16]                              ( 1024 f)
#define OFF_ST   31520    // float st[4][20]                                   (   80 f)
#define OFF_GATE 31600    // float gate[2][4][8]                               (   64 f)
#define OFF_XB   31664    // float xb[2][4]                                    (    8 f)
#define SMEM_FLOATS 31672
#define SMEM_BYTES  (SMEM_FLOATS * 4)

typedef unsigned long long u64;

__device__ float g_gate[(size_t)B_ * T_ * 8];

__device__ __forceinline__ float ex2f(float a)
{
    float r;
    asm("ex2.approx.ftz.f32 %0, %1;" : "=f"(r) : "f"(a));
    return r;
}
__device__ __forceinline__ u64 fma2(u64 b, u64 c, u64 a)   // b*c + a
{
    u64 d;
    asm("fma.rn.f32x2 %0, %1, %2, %3;" : "=l"(d) : "l"(b), "l"(c), "l"(a));
    return d;
}
__device__ __forceinline__ u64 mul2(u64 a, u64 b)
{
    u64 d;
    asm("mul.rn.f32x2 %0, %1, %2;" : "=l"(d) : "l"(a), "l"(b));
    return d;
}
__device__ __forceinline__ float2 upk(u64 a)
{
    float2 f;
    asm("mov.b64 {%0, %1}, %2;" : "=f"(f.x), "=f"(f.y) : "l"(a));
    return f;
}
__device__ __forceinline__ u64 pk2(float lo, float hi)
{
    u64 d;
    asm("mov.b64 %0, {%1, %2};" : "=l"(d) : "f"(lo), "f"(hi));
    return d;
}

// ---------------------------------------------------------------------------
// Kernel 1: gate[b,t,:] = softmax(relu(x*W1+b1) @ W2 + b2). One thread per (b,t).
// ---------------------------------------------------------------------------
__global__ void gate_kernel(const float* __restrict__ x,
                            const float* __restrict__ W1,
                            const float* __restrict__ b1,
                            const float* __restrict__ W2,
                            const float* __restrict__ b2)
{
    int idx = blockIdx.x * blockDim.x + threadIdx.x;
    if (idx >= B_ * T_) return;
    float xv = x[idx];

    float lg[8];
#pragma unroll
    for (int c = 0; c < 8; c++) lg[c] = __ldg(&b2[c]);
#pragma unroll
    for (int jj = 0; jj < 16; jj++) {
        float h = fmaxf(fmaf(xv, __ldg(&W1[jj]), __ldg(&b1[jj])), 0.0f);
#pragma unroll
        for (int c = 0; c < 8; c++)
            lg[c] = fmaf(h, __ldg(&W2[jj * 8 + c]), lg[c]);
    }
    float m = lg[0];
#pragma unroll
    for (int c = 1; c < 8; c++) m = fmaxf(m, lg[c]);
    float e[8], ssum = 0.0f;
#pragma unroll
    for (int c = 0; c < 8; c++) { e[c] = __expf(lg[c] - m); ssum += e[c]; }
    float inv = 1.0f / ssum;
#pragma unroll
    for (int c = 0; c < 8; c++) g_gate[(size_t)idx * 8 + c] = e[c] * inv;
}

// ---------------------------------------------------------------------------
// Kernel 2: recurrent scan. 128 blocks x 512 threads, 4 batches per block.
// R10 base + micro-opts:
//   (1) cell indices ci (dp/50) hoisted out of the t-loop (thread-static)
//   (2) h' moved OFF the dot-chain seed: seed = mul2(uk, xp); e = dot + hvn
//       -> the 8-fma2 ss chain overlaps the dot chains instead of gating them
//   (3) prefetch g_gate/x addressing strength-reduced to pointer increments
// ---------------------------------------------------------------------------
__global__ void __launch_bounds__(TPB, 1)
scan_kernel(const float* __restrict__ x,
            const float* __restrict__ S,
            const float* __restrict__ U,
            const float* __restrict__ A,
            float* __restrict__ out)
{
    extern __shared__ float sm[];
    const int tid = threadIdx.x;
    const int b0  = blockIdx.x * 4;

    // ---------------- stage S', A^T, (u2, k') ----------------
    for (int idx = tid; idx < NP * 16; idx += TPB) {
        int p = idx >> 4, k = idx & 15;
        sm[OFF_SQ + (k >> 2) * 3200 + (p << 2) + (k & 3)] = TWO_L2E * S[idx];
        sm[OFF_AT + k * 804 + p] = A[idx];
    }
    for (int p = tid; p < NP; p += TPB) {
        float acc = 0.0f;
#pragma unroll
        for (int k = 0; k < 16; k++) { float v = S[p * 16 + k]; acc = fmaf(v, v, acc); }
        float uv = U[p];
        sm[OFF_UK + 2 * p]     = TWO_L2E * uv;
        sm[OFF_UK + 2 * p + 1] = L2E * fmaf(uv, uv, acc);
    }
    if (tid < 32) {
        sm[OFF_GATE + tid] = g_gate[((size_t)(b0 + (tid >> 3)) * T_) * 8 + (tid & 7)];
        if (tid < 4) sm[OFF_XB + tid] = x[(size_t)(b0 + tid) * T_];
    }
    __syncthreads();

    const int b    = tid & 3;    // phase A batch
    const int pp   = tid >> 2;   // phase A dpair lane (0..127)
    const int nn   = tid & 15;   // phase B output dim
    const int j    = tid >> 4;   // phase B chunk lane (0..31)
    const int lane = tid & 31;
    const int wrp  = tid >> 5;

    // thread-static cell indices (hoisted out of the t-loop)
    int ciA[4];
#pragma unroll
    for (int i = 0; i < 3; i++) ciA[i] = (unsigned)(pp + 128 * i) / 50u;
    ciA[3] = 7;                      // dp 384..399 -> pairs 768..799

    // strength-reduced prefetch pointers (warp 0 only uses them)
    const float* gptr = &g_gate[((size_t)(b0 + (tid >> 3)) * T_ + 1) * 8 + (tid & 7)];
    const float* xptr = (tid < 4) ? &x[(size_t)(b0 + tid) * T_ + 1] : x;

    const ulonglong2* Sq2 = (const ulonglong2*)(sm + OFF_SQ);
    const ulonglong2* At2 = (const ulonglong2*)(sm + OFF_AT + nn * 804);
    const ulonglong2* Wb2 = (const ulonglong2*)(sm + OFF_W);

    // -------- A register cache: 6 chunks per thread, static across t --------
    ulonglong2 Ac[6];
#pragma unroll
    for (int i = 0; i < 6; i++) Ac[i] = At2[j + 32 * i];

    // packed state (8 x f32x2); xv = raw x_t
    // hvn = -l2e*(|s|^2 + xv^2) scalar (applied at chain END); xp = (xv, -1)
    u64 s0 = 0, s1 = 0, s2 = 0, s3 = 0, s4 = 0, s5 = 0, s6 = 0, s7 = 0;
    float xv = sm[OFF_XB + b];
    float hvn = -L2E * xv * xv;
    u64 xp = pk2(xv, -1.0f);

    for (int t = 0; t < T_; t++) {
        const int par = t & 1;

        // next-step gate/x loads (committed after bar1, consumed at step end)
        float gpre = 0.f, xpre = 0.f;
        const bool pf = (tid < 32) && (t + 1 < T_);
        if (pf) {
            gpre = *gptr; gptr += 8;
            if (tid < 4) { xpre = *xptr; xptr += 1; }
        }

        // ---------------- phase A: pairs (2dp, 2dp+1) ----------------
        {
            const float* gsh = sm + OFF_GATE + par * 32 + b * 8;

            auto dpair = [&](int dp, int ci) {
                const int p0 = 2 * dp;
                ulonglong2 q0a = Sq2[p0],        q0b = Sq2[p0 + 1];
                ulonglong2 q1a = Sq2[800 + p0],  q1b = Sq2[801 + p0];
                ulonglong2 q2a = Sq2[1600 + p0], q2b = Sq2[1601 + p0];
                ulonglong2 q3a = Sq2[2400 + p0], q3b = Sq2[2401 + p0];
                ulonglong2 ukp = *(const ulonglong2*)(sm + OFF_UK + 4 * dp);
                float g = gsh[ci];

                u64 da = mul2(ukp.x, xp);         // (u2*xv, -k') — no hs dep
                da = fma2(q0a.x, s0, da);
                da = fma2(q0a.y, s1, da);
                da = fma2(q1a.x, s2, da);
                da = fma2(q1a.y, s3, da);
                da = fma2(q2a.x, s4, da);
                da = fma2(q2a.y, s5, da);
                da = fma2(q3a.x, s6, da);
                da = fma2(q3a.y, s7, da);
                float2 fa = upk(da);
                float e0 = (fa.x + fa.y) + hvn;

                u64 db = mul2(ukp.y, xp);
                db = fma2(q0b.x, s0, db);
                db = fma2(q0b.y, s1, db);
                db = fma2(q1b.x, s2, db);
                db = fma2(q1b.y, s3, db);
                db = fma2(q2b.x, s4, db);
                db = fma2(q2b.y, s5, db);
                db = fma2(q3b.x, s6, db);
                db = fma2(q3b.y, s7, db);
                float2 fb = upk(db);
                float e1 = (fb.x + fb.y) + hvn;

                *(float2*)(sm + OFF_W + b * 808 + p0) =
                    make_float2(g * ex2f(e0), g * ex2f(e1));
            };
#pragma unroll
            for (int i = 0; i < 3; i++) dpair(pp + 128 * i, ciA[i]);
            if (pp >= 112) dpair(272 + pp, ciA[3]);   // dp 384..399
        }
        __syncthreads();                             // bar 1

        // commit prefetched gate/x for t+1
        if (pf) {
            sm[OFF_GATE + (par ^ 1) * 32 + tid] = gpre;
            if (tid < 4) sm[OFF_XB + (par ^ 1) * 4 + tid] = xpre;
        }

        // ---------------- phase B: s_new[b][n] = sum_p w[b][p]*A[p][n] -------
        u64 c0 = 0, c1 = 0, c2 = 0, c3 = 0;
        auto chunkB = [&](int p4, ulonglong2 av) {
            ulonglong2 w0 = Wb2[p4];
            ulonglong2 w1 = Wb2[202 + p4];
            ulonglong2 w2 = Wb2[404 + p4];
            ulonglong2 w3 = Wb2[606 + p4];
            c0 = fma2(av.x, w0.x, c0); c0 = fma2(av.y, w0.y, c0);
            c1 = fma2(av.x, w1.x, c1); c1 = fma2(av.y, w1.y, c1);
            c2 = fma2(av.x, w2.x, c2); c2 = fma2(av.y, w2.y, c2);
            c3 = fma2(av.x, w3.x, c3); c3 = fma2(av.y, w3.y, c3);
        };
#pragma unroll
        for (int i = 0; i < 6; i++) chunkB(j + 32 * i, Ac[i]);
        if (j >= 24) chunkB(168 + j, At2[168 + j]);  // tail chunks 192..199

        float2 f0 = upk(c0), f1 = upk(c1), f2 = upk(c2), f3 = upk(c3);
        float a0 = f0.x + f0.y, a1 = f1.x + f1.y, a2 = f2.x + f2.y, a3 = f3.x + f3.y;
        a0 += __shfl_xor_sync(0xffffffffu, a0, 16);
        a1 += __shfl_xor_sync(0xffffffffu, a1, 16);
        a2 += __shfl_xor_sync(0xffffffffu, a2, 16);
        a3 += __shfl_xor_sync(0xffffffffu, a3, 16);
        if (lane < 16) {
            sm[OFF_RED +       wrp * 16 + lane] = a0;
            sm[OFF_RED + 256 + wrp * 16 + lane] = a1;
            sm[OFF_RED + 512 + wrp * 16 + lane] = a2;
            sm[OFF_RED + 768 + wrp * 16 + lane] = a3;
        }
        __syncthreads();                             // bar 2

        // ---------------- final reduce + output (256 threads, 4+shfl) --------
        if (tid < 256) {
            const int bb = tid >> 6, n2 = (tid >> 2) & 15, g = tid & 3;
            const float* r = sm + OFF_RED + bb * 256 + g * 16 + n2;
            float v = (r[0] + r[64]) + (r[128] + r[192]);   // warps g, g+4, g+8, g+12
            v += __shfl_xor_sync(0xffffffffu, v, 1);
            v += __shfl_xor_sync(0xffffffffu, v, 2);
            if (g == 0) {
                sm[OFF_ST + bb * 20 + n2] = v;
                if (n2 == 15) out[(size_t)(b0 + bb) * T_ + t] = v;
            }
        }
        __syncthreads();                             // bar 3

        // reload packed state; hvn chain runs concurrent with next phase A
        {
            const ulonglong2* st2 = (const ulonglong2*)(sm + OFF_ST + b * 20);
            ulonglong2 u0 = st2[0], u1 = st2[1], u2 = st2[2], u3 = st2[3];
            s0 = u0.x; s1 = u0.y; s2 = u1.x; s3 = u1.y;
            s4 = u2.x; s5 = u2.y; s6 = u3.x; s7 = u3.y;
            xv = sm[OFF_XB + (par ^ 1) * 4 + b];
            u64 acc = mul2(s0, s0);
            acc = fma2(s1, s1, acc);
            acc = fma2(s2, s2, acc);
            acc = fma2(s3, s3, acc);
            acc = fma2(s4, s4, acc);
            acc = fma2(s5, s5, acc);
            acc = fma2(s6, s6, acc);
            acc = fma2(s7, s7, acc);
            float2 fs = upk(acc);
            hvn = -L2E * fmaf(xv, xv, fs.x + fs.y);
            xp = pk2(xv, -1.0f);
        }
    }
}

// ---------------------------------------------------------------------------
extern "C" void kernel_launch(void* const* d_in, const int* in_sizes, int n_in,
                              void* d_out, int out_size)
{
    const float* x  = (const float*)d_in[0];
    const float* S  = (const float*)d_in[1];
    const float* U  = (const float*)d_in[2];
    const float* A  = (const float*)d_in[3];
    const float* W1 = (const float*)d_in[4];
    const float* b1 = (const float*)d_in[5];
    const float* W2 = (const float*)d_in[6];
    const float* b2 = (const float*)d_in[7];
    float* out = (float*)d_out;

    cudaFuncSetAttribute(scan_kernel,
                         cudaFuncAttributeMaxDynamicSharedMemorySize, SMEM_BYTES);

    gate_kernel<<<(B_ * T_ + 255) / 256, 256>>>(x, W1, b1, W2, b2);
    scan_kernel<<<NBLK, TPB, SMEM_BYTES>>>(x, S, U, A, out);
}

// round 17
// speedup vs baseline: 1.4245x; 1.0031x over previous
#include <cuda_runtime.h>
#include <cuda_bf16.h>
#include <cstdint>
#include <cstddef>

#define B_   512
#define T_   2048
#define NP   800          // C*M pairs
#define TPB  512
#define NBLK 128          // B_/4, 4 batches per block

#define L2E     1.4426950408889634f
#define TWO_L2E 2.8853900817779268f

// ---- shared layout (float offsets) ----
#define OFF_SQ   0        // Sq[4 quad][800][4] : S quads transposed, *2*log2e (12800 f)
#define OFF_AT   12800    // float at[16][804]  : A transposed, padded         (12864 f)
#define OFF_UK   25664    // float2 uk[800]     : (2*l2e*U, l2e*(|S|^2+U^2))   ( 1600 f)
#define OFF_W    27264    // float w[4][808]    : stride 808                   ( 3232 f)
#define OFF_RED  30496    // float red[4][16][16]                              ( 1024 f)
#define OFF_ST   31520    // float st[4][20]                                   (   80 f)
#define OFF_GATE 31600    // float gate[2][4][8]                               (   64 f)
#define OFF_XB   31664    // float xb[2][4]                                    (    8 f)
#define SMEM_FLOATS 31672
#define SMEM_BYTES  (SMEM_FLOATS * 4)

typedef unsigned long long u64;

__device__ float g_gate[(size_t)B_ * T_ * 8];

__device__ __forceinline__ float ex2f(float a)
{
    float r;
    asm("ex2.approx.ftz.f32 %0, %1;" : "=f"(r) : "f"(a));
    return r;
}
__device__ __forceinline__ u64 fma2(u64 b, u64 c, u64 a)   // b*c + a
{
    u64 d;
    asm("fma.rn.f32x2 %0, %1, %2, %3;" : "=l"(d) : "l"(b), "l"(c), "l"(a));
    return d;
}
__device__ __forceinline__ u64 mul2(u64 a, u64 b)
{
    u64 d;
    asm("mul.rn.f32x2 %0, %1, %2;" : "=l"(d) : "l"(a), "l"(b));
    return d;
}
__device__ __forceinline__ float2 upk(u64 a)
{
    float2 f;
    asm("mov.b64 {%0, %1}, %2;" : "=f"(f.x), "=f"(f.y) : "l"(a));
    return f;
}
__device__ __forceinline__ u64 pk2(float lo, float hi)
{
    u64 d;
    asm("mov.b64 %0, {%1, %2};" : "=l"(d) : "f"(lo), "f"(hi));
    return d;
}

// ---------------------------------------------------------------------------
// Kernel 1: gate[b,t,:] = softmax(relu(x*W1+b1) @ W2 + b2). One thread per (b,t).
// ---------------------------------------------------------------------------
__global__ void gate_kernel(const float* __restrict__ x,
                            const float* __restrict__ W1,
                            const float* __restrict__ b1,
                            const float* __restrict__ W2,
                            const float* __restrict__ b2)
{
    int idx = blockIdx.x * blockDim.x + threadIdx.x;
    if (idx >= B_ * T_) return;
    float xv = x[idx];

    float lg[8];
#pragma unroll
    for (int c = 0; c < 8; c++) lg[c] = __ldg(&b2[c]);
#pragma unroll
    for (int jj = 0; jj < 16; jj++) {
        float h = fmaxf(fmaf(xv, __ldg(&W1[jj]), __ldg(&b1[jj])), 0.0f);
#pragma unroll
        for (int c = 0; c < 8; c++)
            lg[c] = fmaf(h, __ldg(&W2[jj * 8 + c]), lg[c]);
    }
    float m = lg[0];
#pragma unroll
    for (int c = 1; c < 8; c++) m = fmaxf(m, lg[c]);
    float e[8], ssum = 0.0f;
#pragma unroll
    for (int c = 0; c < 8; c++) { e[c] = __expf(lg[c] - m); ssum += e[c]; }
    float inv = 1.0f / ssum;
#pragma unroll
    for (int c = 0; c < 8; c++) g_gate[(size_t)idx * 8 + c] = e[c] * inv;
}

// ---------------------------------------------------------------------------
// Kernel 2: recurrent scan. 128 blocks x 512 threads, 4 batches per block.
// Exactly the 3018us R10 kernel + two pure instruction deletions:
//   (1) cell indices ci (dp/50) hoisted out of the t-loop (thread-static)
//   (2) prefetch g_gate/x addressing strength-reduced to pointer increments
// The hs-seeded 9-fma2 dot chain of R10 is kept verbatim.
// ---------------------------------------------------------------------------
__global__ void __launch_bounds__(TPB, 1)
scan_kernel(const float* __restrict__ x,
            const float* __restrict__ S,
            const float* __restrict__ U,
            const float* __restrict__ A,
            float* __restrict__ out)
{
    extern __shared__ float sm[];
    const int tid = threadIdx.x;
    const int b0  = blockIdx.x * 4;

    // ---------------- stage S', A^T, (u2, k') ----------------
    for (int idx = tid; idx < NP * 16; idx += TPB) {
        int p = idx >> 4, k = idx & 15;
        sm[OFF_SQ + (k >> 2) * 3200 + (p << 2) + (k & 3)] = TWO_L2E * S[idx];
        sm[OFF_AT + k * 804 + p] = A[idx];
    }
    for (int p = tid; p < NP; p += TPB) {
        float acc = 0.0f;
#pragma unroll
        for (int k = 0; k < 16; k++) { float v = S[p * 16 + k]; acc = fmaf(v, v, acc); }
        float uv = U[p];
        sm[OFF_UK + 2 * p]     = TWO_L2E * uv;
        sm[OFF_UK + 2 * p + 1] = L2E * fmaf(uv, uv, acc);
    }
    if (tid < 32) {
        sm[OFF_GATE + tid] = g_gate[((size_t)(b0 + (tid >> 3)) * T_) * 8 + (tid & 7)];
        if (tid < 4) sm[OFF_XB + tid] = x[(size_t)(b0 + tid) * T_];
    }
    __syncthreads();

    const int b    = tid & 3;    // phase A batch
    const int pp   = tid >> 2;   // phase A dpair lane (0..127)
    const int nn   = tid & 15;   // phase B output dim
    const int j    = tid >> 4;   // phase B chunk lane (0..31)
    const int lane = tid & 31;
    const int wrp  = tid >> 5;

    // thread-static cell indices (hoisted out of the t-loop)
    int ciA[4];
#pragma unroll
    for (int i = 0; i < 3; i++) ciA[i] = (unsigned)(pp + 128 * i) / 50u;
    ciA[3] = 7;                      // dp 384..399 -> pairs 768..799

    // strength-reduced prefetch pointers (warp 0 only uses them)
    const float* gptr = &g_gate[((size_t)(b0 + (tid >> 3)) * T_ + 1) * 8 + (tid & 7)];
    const float* xptr = (tid < 4) ? &x[(size_t)(b0 + tid) * T_ + 1] : x;

    const ulonglong2* Sq2 = (const ulonglong2*)(sm + OFF_SQ);
    const ulonglong2* At2 = (const ulonglong2*)(sm + OFF_AT + nn * 804);
    const ulonglong2* Wb2 = (const ulonglong2*)(sm + OFF_W);

    // -------- A register cache: 6 chunks per thread, static across t --------
    ulonglong2 Ac[6];
#pragma unroll
    for (int i = 0; i < 6; i++) Ac[i] = At2[j + 32 * i];

    // packed state (8 x f32x2); xv = raw x_t
    // hs = (-h', 0) seed; xp = (xv, -1) uk-fold multiplier
    u64 s0 = 0, s1 = 0, s2 = 0, s3 = 0, s4 = 0, s5 = 0, s6 = 0, s7 = 0;
    float xv = sm[OFF_XB + b];
    u64 hs = pk2(-L2E * xv * xv, 0.0f);
    u64 xp = pk2(xv, -1.0f);

    for (int t = 0; t < T_; t++) {
        const int par = t & 1;

        // next-step gate/x loads (committed after bar1, consumed at step end)
        float gpre = 0.f, xpre = 0.f;
        const bool pf = (tid < 32) && (t + 1 < T_);
        if (pf) {
            gpre = *gptr; gptr += 8;
            if (tid < 4) { xpre = *xptr; xptr += 1; }
        }

        // ---------------- phase A: pairs (2dp, 2dp+1) ----------------
        {
            const float* gsh = sm + OFF_GATE + par * 32 + b * 8;

            auto dpair = [&](int dp, int ci) {
                const int p0 = 2 * dp;
                ulonglong2 q0a = Sq2[p0],        q0b = Sq2[p0 + 1];
                ulonglong2 q1a = Sq2[800 + p0],  q1b = Sq2[801 + p0];
                ulonglong2 q2a = Sq2[1600 + p0], q2b = Sq2[1601 + p0];
                ulonglong2 q3a = Sq2[2400 + p0], q3b = Sq2[2401 + p0];
                ulonglong2 ukp = *(const ulonglong2*)(sm + OFF_UK + 4 * dp);
                float g = gsh[ci];

                u64 da = fma2(ukp.x, xp, hs);     // (u2*xv - h', -k')
                da = fma2(q0a.x, s0, da);
                da = fma2(q0a.y, s1, da);
                da = fma2(q1a.x, s2, da);
                da = fma2(q1a.y, s3, da);
                da = fma2(q2a.x, s4, da);
                da = fma2(q2a.y, s5, da);
                da = fma2(q3a.x, s6, da);
                da = fma2(q3a.y, s7, da);
                float2 fa = upk(da);
                float e0 = fa.x + fa.y;

                u64 db = fma2(ukp.y, xp, hs);
                db = fma2(q0b.x, s0, db);
                db = fma2(q0b.y, s1, db);
                db = fma2(q1b.x, s2, db);
                db = fma2(q1b.y, s3, db);
                db = fma2(q2b.x, s4, db);
                db = fma2(q2b.y, s5, db);
                db = fma2(q3b.x, s6, db);
                db = fma2(q3b.y, s7, db);
                float2 fb = upk(db);
                float e1 = fb.x + fb.y;

                *(float2*)(sm + OFF_W + b * 808 + p0) =
                    make_float2(g * ex2f(e0), g * ex2f(e1));
            };
#pragma unroll
            for (int i = 0; i < 3; i++) dpair(pp + 128 * i, ciA[i]);
            if (pp >= 112) dpair(272 + pp, ciA[3]);   // dp 384..399
        }
        __syncthreads();                             // bar 1

        // commit prefetched gate/x for t+1
        if (pf) {
            sm[OFF_GATE + (par ^ 1) * 32 + tid] = gpre;
            if (tid < 4) sm[OFF_XB + (par ^ 1) * 4 + tid] = xpre;
        }

        // ---------------- phase B: s_new[b][n] = sum_p w[b][p]*A[p][n] -------
        u64 c0 = 0, c1 = 0, c2 = 0, c3 = 0;
        auto chunkB = [&](int p4, ulonglong2 av) {
            ulonglong2 w0 = Wb2[p4];
            ulonglong2 w1 = Wb2[202 + p4];
            ulonglong2 w2 = Wb2[404 + p4];
            ulonglong2 w3 = Wb2[606 + p4];
            c0 = fma2(av.x, w0.x, c0); c0 = fma2(av.y, w0.y, c0);
            c1 = fma2(av.x, w1.x, c1); c1 = fma2(av.y, w1.y, c1);
            c2 = fma2(av.x, w2.x, c2); c2 = fma2(av.y, w2.y, c2);
            c3 = fma2(av.x, w3.x, c3); c3 = fma2(av.y, w3.y, c3);
        };
#pragma unroll
        for (int i = 0; i < 6; i++) chunkB(j + 32 * i, Ac[i]);
        if (j >= 24) chunkB(168 + j, At2[168 + j]);  // tail chunks 192..199

        float2 f0 = upk(c0), f1 = upk(c1), f2 = upk(c2), f3 = upk(c3);
        float a0 = f0.x + f0.y, a1 = f1.x + f1.y, a2 = f2.x + f2.y, a3 = f3.x + f3.y;
        a0 += __shfl_xor_sync(0xffffffffu, a0, 16);
        a1 += __shfl_xor_sync(0xffffffffu, a1, 16);
        a2 += __shfl_xor_sync(0xffffffffu, a2, 16);
        a3 += __shfl_xor_sync(0xffffffffu, a3, 16);
        if (lane < 16) {
            sm[OFF_RED +       wrp * 16 + lane] = a0;
            sm[OFF_RED + 256 + wrp * 16 + lane] = a1;
            sm[OFF_RED + 512 + wrp * 16 + lane] = a2;
            sm[OFF_RED + 768 + wrp * 16 + lane] = a3;
        }
        __syncthreads();                             // bar 2

        // ---------------- final reduce + output (256 threads, 4+shfl) --------
        if (tid < 256) {
            const int bb = tid >> 6, n2 = (tid >> 2) & 15, g = tid & 3;
            const float* r = sm + OFF_RED + bb * 256 + g * 16 + n2;
            float v = (r[0] + r[64]) + (r[128] + r[192]);   // warps g, g+4, g+8, g+12
            v += __shfl_xor_sync(0xffffffffu, v, 1);
            v += __shfl_xor_sync(0xffffffffu, v, 2);
            if (g == 0) {
                sm[OFF_ST + bb * 20 + n2] = v;
                if (n2 == 15) out[(size_t)(b0 + bb) * T_ + t] = v;
            }
        }
        __syncthreads();                             // bar 3

        // reload packed state; recompute h', xp locally
        {
            const ulonglong2* st2 = (const ulonglong2*)(sm + OFF_ST + b * 20);
            ulonglong2 u0 = st2[0], u1 = st2[1], u2 = st2[2], u3 = st2[3];
            s0 = u0.x; s1 = u0.y; s2 = u1.x; s3 = u1.y;
            s4 = u2.x; s5 = u2.y; s6 = u3.x; s7 = u3.y;
            xv = sm[OFF_XB + (par ^ 1) * 4 + b];
            u64 acc = mul2(s0, s0);
            acc = fma2(s1, s1, acc);
            acc = fma2(s2, s2, acc);
            acc = fma2(s3, s3, acc);
            acc = fma2(s4, s4, acc);
            acc = fma2(s5, s5, acc);
            acc = fma2(s6, s6, acc);
            acc = fma2(s7, s7, acc);
            float2 fs = upk(acc);
            float hv = fmaf(xv, xv, fs.x + fs.y);
            hs = pk2(-L2E * hv, 0.0f);
            xp = pk2(xv, -1.0f);
        }
    }
}

// ---------------------------------------------------------------------------
extern "C" void kernel_launch(void* const* d_in, const int* in_sizes, int n_in,
                              void* d_out, int out_size)
{
    const float* x  = (const float*)d_in[0];
    const float* S  = (const float*)d_in[1];
    const float* U  = (const float*)d_in[2];
    const float* A  = (const float*)d_in[3];
    const float* W1 = (const float*)d_in[4];
    const float* b1 = (const float*)d_in[5];
    const float* W2 = (const float*)d_in[6];
    const float* b2 = (const float*)d_in[7];
    float* out = (float*)d_out;

    cudaFuncSetAttribute(scan_kernel,
                         cudaFuncAttributeMaxDynamicSharedMemorySize, SMEM_BYTES);

    gate_kernel<<<(B_ * T_ + 255) / 256, 256>>>(x, W1, b1, W2, b2);
    scan_kernel<<<NBLK, TPB, SMEM_BYTES>>>(x, S, U, A, out);
}